// round 1
// baseline (speedup 1.0000x reference)
#include <cuda_runtime.h>

// ---------------------------------------------------------------------------
// BasicDMPNN on GB300 — algebraically restructured:
//   * (x[src], edge_attr) -> 476-row lookup tables for ab@Wi+bi and ab@Wu1[:192]+bu1
//   * agg@Wu1[192:] computed at node level
//   * msg computed per (node, attr) pair (200k rows), edges become gather+scatter
// ---------------------------------------------------------------------------

#define NMAX 50000
#define EMAX 800000
#define MMAX 2000
#define NTAB 476          // 119 atom types * 4 bond types

__device__ __align__(16) float g_bias[NTAB * 128];     // ab@Wu1[:192]+bu1 table
__device__ __align__(16) float g_msgInit[NTAB * 128];  // relu(ab@Wi+bi) table
__device__ __align__(16) float g_agg[NMAX * 128];      // segment-sum accumulator
__device__ __align__(16) float g_msgTable[NMAX * 4 * 128];
__device__ __align__(16) float g_mol[MMAX * 128];

// ---------------------------------------------------------------------------
__global__ void zero_agg_kernel() {
    float4 z = make_float4(0.f, 0.f, 0.f, 0.f);
    float4* p = (float4*)g_agg;
    int n4 = NMAX * 32;
    for (int i = blockIdx.x * blockDim.x + threadIdx.x; i < n4;
         i += gridDim.x * blockDim.x)
        p[i] = z;
}

__global__ void zero_mol_kernel() {
    float4 z = make_float4(0.f, 0.f, 0.f, 0.f);
    float4* p = (float4*)g_mol;
    int n4 = MMAX * 32;
    for (int i = blockIdx.x * blockDim.x + threadIdx.x; i < n4;
         i += gridDim.x * blockDim.x)
        p[i] = z;
}

// ---------------------------------------------------------------------------
// Build the two 476x128 tables.
// blockIdx.x = t*4 + a (atom type t, bond type a), 128 threads = output col j.
__global__ void table_kernel(const float* __restrict__ atom_table,
                             const float* __restrict__ bond_table,
                             const float* __restrict__ Wi,
                             const float* __restrict__ bi,
                             const float* __restrict__ Wu1,
                             const float* __restrict__ bu1) {
    int t = blockIdx.x >> 2;
    int a = blockIdx.x & 3;
    int j = threadIdx.x;

    __shared__ float sAtom[128];
    __shared__ float sBond[64];
    sAtom[j] = atom_table[t * 128 + j];
    if (j < 64) sBond[j] = bond_table[a * 64 + j];
    __syncthreads();

    float accI = bi[j];
    float accB = bu1[j];
#pragma unroll 8
    for (int k = 0; k < 128; k++) {
        float av = sAtom[k];
        accI = fmaf(av, Wi[k * 128 + j], accI);
        accB = fmaf(av, Wu1[k * 128 + j], accB);
    }
#pragma unroll 8
    for (int k = 0; k < 64; k++) {
        float bv = sBond[k];
        accI = fmaf(bv, Wi[(128 + k) * 128 + j], accI);
        accB = fmaf(bv, Wu1[(128 + k) * 128 + j], accB);
    }
    g_msgInit[blockIdx.x * 128 + j] = fmaxf(accI, 0.f);
    g_bias[blockIdx.x * 128 + j] = accB;
}

// ---------------------------------------------------------------------------
// Edge scatter: for each edge e, agg[dst[e]] += table[row(e)].
// useX=1: row = x[src]*4 + attr (initial message, 476-row table)
// useX=0: row = src*4 + attr   (msgTable, 200k rows)
// One warp per edge, float4 per lane, vector red.
__global__ void scatter_kernel(const int* __restrict__ src,
                               const int* __restrict__ dst,
                               const int* __restrict__ attr,
                               const int* __restrict__ x,
                               int E, int useX) {
    const float* table = useX ? g_msgInit : g_msgTable;
    int lane = threadIdx.x & 31;
    int w = (blockIdx.x * blockDim.x + threadIdx.x) >> 5;
    int nw = (gridDim.x * blockDim.x) >> 5;
    for (int e = w; e < E; e += nw) {
        int s = src[e];
        int d = dst[e];
        int a = attr[e];
        int r = useX ? (x[s] * 4 + a) : (s * 4 + a);
        float4 v = ((const float4*)(table + (size_t)r * 128))[lane];
        float* out = g_agg + (size_t)d * 128 + lane * 4;
        asm volatile("red.global.add.v4.f32 [%0], {%1,%2,%3,%4};"
                     :: "l"(out), "f"(v.x), "f"(v.y), "f"(v.z), "f"(v.w)
                     : "memory");
    }
}

// ---------------------------------------------------------------------------
// Update pass at node level:
//   aggW[n]      = agg[n] @ Wu1[192:320]                       [64 x 128]
//   for a in 0..3:
//     h          = relu(aggW[n] + g_bias[x[n]*4+a])
//     msgTable[n*4+a] = relu(h @ Wu2 + bu2)
// 512 threads, 64 nodes per block. Dynamic smem 128KB:
//   sW (128x128 weights), sA (64x128 input / h), sM (64x128 aggW)
#define FMA4(acc, s, wv)                       \
    {                                          \
        acc.x = fmaf((s), (wv).x, acc.x);      \
        acc.y = fmaf((s), (wv).y, acc.y);      \
        acc.z = fmaf((s), (wv).z, acc.z);      \
        acc.w = fmaf((s), (wv).w, acc.w);      \
    }

__device__ __forceinline__ void gemm_64x128(const float4* __restrict__ sA4,
                                            const float4* __restrict__ sW4,
                                            int rbase, int lane, float4 acc[4]) {
    acc[0] = acc[1] = acc[2] = acc[3] = make_float4(0.f, 0.f, 0.f, 0.f);
#pragma unroll 4
    for (int k4 = 0; k4 < 32; k4++) {
        float4 a0 = sA4[(rbase + 0) * 32 + k4];
        float4 a1 = sA4[(rbase + 1) * 32 + k4];
        float4 a2 = sA4[(rbase + 2) * 32 + k4];
        float4 a3 = sA4[(rbase + 3) * 32 + k4];
        const float4* wp = sW4 + (k4 * 4) * 32 + lane;
        float4 w0 = wp[0];
        float4 w1 = wp[32];
        float4 w2 = wp[64];
        float4 w3 = wp[96];
        FMA4(acc[0], a0.x, w0); FMA4(acc[0], a0.y, w1);
        FMA4(acc[0], a0.z, w2); FMA4(acc[0], a0.w, w3);
        FMA4(acc[1], a1.x, w0); FMA4(acc[1], a1.y, w1);
        FMA4(acc[1], a1.z, w2); FMA4(acc[1], a1.w, w3);
        FMA4(acc[2], a2.x, w0); FMA4(acc[2], a2.y, w1);
        FMA4(acc[2], a2.z, w2); FMA4(acc[2], a2.w, w3);
        FMA4(acc[3], a3.x, w0); FMA4(acc[3], a3.y, w1);
        FMA4(acc[3], a3.z, w2); FMA4(acc[3], a3.w, w3);
    }
}

__global__ void __launch_bounds__(512, 1)
update_kernel(const int* __restrict__ x,
              const float* __restrict__ Wu1agg,   // Wu1 + 192*128
              const float* __restrict__ Wu2,
              const float* __restrict__ bu2,
              int N) {
    extern __shared__ float smem[];
    float4* sW4 = (float4*)smem;                 // 4096 float4 (64KB)
    float4* sA4 = (float4*)(smem + 16384);       // 2048 float4 (32KB)
    float4* sM4 = (float4*)(smem + 16384 + 8192);// 2048 float4 (32KB)
    __shared__ int sX[64];

    int tid = threadIdx.x;
    int lane = tid & 31;
    int w = tid >> 5;
    int rbase = w * 4;   // 16 warps * 4 rows = 64 rows
    int nb = blockIdx.x * 64;

    // Load Wu1agg and agg rows
    const float4* W14 = (const float4*)Wu1agg;
#pragma unroll
    for (int i = tid; i < 4096; i += 512) sW4[i] = W14[i];
    const float4* agg4 = (const float4*)g_agg;
#pragma unroll
    for (int i = tid; i < 2048; i += 512) {
        int row = i >> 5;
        sA4[i] = (nb + row < N) ? agg4[(nb + row) * 32 + (i & 31)]
                                : make_float4(0.f, 0.f, 0.f, 0.f);
    }
    if (tid < 64) sX[tid] = (nb + tid < N) ? x[nb + tid] * 4 : 0;
    __syncthreads();

    // aggW = agg @ Wu1agg
    float4 acc[4];
    gemm_64x128(sA4, sW4, rbase, lane, acc);
#pragma unroll
    for (int r = 0; r < 4; r++) sM4[(rbase + r) * 32 + lane] = acc[r];
    __syncthreads();

    // Swap in Wu2
    const float4* W24 = (const float4*)Wu2;
#pragma unroll
    for (int i = tid; i < 4096; i += 512) sW4[i] = W24[i];
    float4 b2 = ((const float4*)bu2)[lane];
    __syncthreads();

    const float4* bias4 = (const float4*)g_bias;
    float4* msg4 = (float4*)g_msgTable;

    for (int a = 0; a < 4; a++) {
        // h = relu(aggW + biasTable[x*4+a]) -> sA
#pragma unroll
        for (int i = tid; i < 2048; i += 512) {
            int row = i >> 5;
            int c4 = i & 31;
            float4 m = sM4[i];
            float4 b = bias4[(sX[row] + a) * 32 + c4];
            float4 h;
            h.x = fmaxf(m.x + b.x, 0.f);
            h.y = fmaxf(m.y + b.y, 0.f);
            h.z = fmaxf(m.z + b.z, 0.f);
            h.w = fmaxf(m.w + b.w, 0.f);
            sA4[i] = h;
        }
        __syncthreads();

        // msg = relu(h @ Wu2 + bu2)
        gemm_64x128(sA4, sW4, rbase, lane, acc);
#pragma unroll
        for (int r = 0; r < 4; r++) {
            int n = nb + rbase + r;
            if (n < N) {
                float4 o;
                o.x = fmaxf(acc[r].x + b2.x, 0.f);
                o.y = fmaxf(acc[r].y + b2.y, 0.f);
                o.z = fmaxf(acc[r].z + b2.z, 0.f);
                o.w = fmaxf(acc[r].w + b2.w, 0.f);
                msg4[(n * 4 + a) * 32 + lane] = o;
            }
        }
        __syncthreads();
    }
}

// ---------------------------------------------------------------------------
// mol_state[batch[n]] += node_state[n]   (node_state lives in g_agg)
__global__ void mol_kernel(const int* __restrict__ batch, int N) {
    int lane = threadIdx.x & 31;
    int w = (blockIdx.x * blockDim.x + threadIdx.x) >> 5;
    int nw = (gridDim.x * blockDim.x) >> 5;
    const float4* ns4 = (const float4*)g_agg;
    for (int n = w; n < N; n += nw) {
        int m = batch[n];
        float4 v = ns4[n * 32 + lane];
        float* out = g_mol + (size_t)m * 128 + lane * 4;
        asm volatile("red.global.add.v4.f32 [%0], {%1,%2,%3,%4};"
                     :: "l"(out), "f"(v.x), "f"(v.y), "f"(v.z), "f"(v.w)
                     : "memory");
    }
}

// ---------------------------------------------------------------------------
// out[m] = relu(mol[m] @ Wr1 + br1) @ Wr2 + br2     (one block per molecule)
__global__ void readout_kernel(const float* __restrict__ Wr1,
                               const float* __restrict__ br1,
                               const float* __restrict__ Wr2,
                               const float* __restrict__ br2,
                               float* __restrict__ out) {
    int m = blockIdx.x;
    int tid = threadIdx.x;  // 256 threads
    __shared__ float sMol[128];
    __shared__ float sRed[8];
    if (tid < 128) sMol[tid] = g_mol[m * 128 + tid];
    __syncthreads();

    float part = 0.f;
#pragma unroll
    for (int jj = 0; jj < 2; jj++) {
        int j = tid + jj * 256;
        float h = br1[j];
#pragma unroll 8
        for (int k = 0; k < 128; k++)
            h = fmaf(sMol[k], Wr1[k * 512 + j], h);
        h = fmaxf(h, 0.f);
        part = fmaf(h, Wr2[j], part);
    }
#pragma unroll
    for (int off = 16; off; off >>= 1)
        part += __shfl_down_sync(0xffffffffu, part, off);
    if ((tid & 31) == 0) sRed[tid >> 5] = part;
    __syncthreads();
    if (tid == 0) {
        float s = br2[0];
#pragma unroll
        for (int i = 0; i < 8; i++) s += sRed[i];
        out[m] = s;
    }
}

// ---------------------------------------------------------------------------
extern "C" void kernel_launch(void* const* d_in, const int* in_sizes, int n_in,
                              void* d_out, int out_size) {
    const int*   x          = (const int*)d_in[0];
    const int*   eattr      = (const int*)d_in[1];
    const int*   eidx       = (const int*)d_in[2];
    const int*   batch      = (const int*)d_in[3];
    const float* atom_table = (const float*)d_in[4];
    const float* bond_table = (const float*)d_in[5];
    const float* Wi         = (const float*)d_in[6];
    const float* bi         = (const float*)d_in[7];
    const float* Wu1        = (const float*)d_in[8];
    const float* bu1        = (const float*)d_in[9];
    const float* Wu2        = (const float*)d_in[10];
    const float* bu2        = (const float*)d_in[11];
    const float* Wr1        = (const float*)d_in[12];
    const float* br1        = (const float*)d_in[13];
    const float* Wr2        = (const float*)d_in[14];
    const float* br2        = (const float*)d_in[15];
    float* out = (float*)d_out;

    int N = in_sizes[0];
    int E = in_sizes[1];
    int M = out_size;
    const int* src = eidx;
    const int* dst = eidx + E;

    cudaFuncSetAttribute(update_kernel,
                         cudaFuncAttributeMaxDynamicSharedMemorySize, 131072);

    // Tables + initial message scatter
    table_kernel<<<NTAB, 128>>>(atom_table, bond_table, Wi, bi, Wu1, bu1);
    zero_agg_kernel<<<1024, 256>>>();
    scatter_kernel<<<2048, 256>>>(src, dst, eattr, x, E, 1);

    int ublocks = (N + 63) / 64;
    for (int p = 0; p < 4; p++) {
        update_kernel<<<ublocks, 512, 131072>>>(x, Wu1 + 192 * 128, Wu2, bu2, N);
        zero_agg_kernel<<<1024, 256>>>();
        scatter_kernel<<<2048, 256>>>(src, dst, eattr, x, E, 0);
    }

    // Molecule pooling + readout
    zero_mol_kernel<<<64, 256>>>();
    mol_kernel<<<512, 256>>>(batch, N);
    readout_kernel<<<M, 256>>>(Wr1, br1, Wr2, br2, out);
}

// round 3
// speedup vs baseline: 1.0053x; 1.0053x over previous
#include <cuda_runtime.h>
#include <cstdint>

// ---------------------------------------------------------------------------
// BasicDMPNN on GB300 — round 3: packed fma.rn.f32x2 update GEMMs.
//   * (x,attr) lookup tables for ab@Wi+bi and ab@Wu1[:192]+bu1 (fp32, exact)
//   * update GEMMs on the FMA pipe with f32x2 (2 MACs/issue), both weight
//     matrices resident in smem, GEMM1 result held in registers
//   * edges remain gather + red.global.add.v4.f32 scatter
// ---------------------------------------------------------------------------

#define NMAX 50000
#define MMAX 2000
#define NTAB 476          // 119 atom types * 4 bond types

__device__ __align__(16) float g_bias[NTAB * 128];     // ab@Wu1[:192]+bu1
__device__ __align__(16) float g_msgInit[NTAB * 128];  // relu(ab@Wi+bi)
__device__ __align__(16) float g_agg[NMAX * 128];
__device__ __align__(16) float g_msgTable[NMAX * 4 * 128];
__device__ __align__(16) float g_mol[MMAX * 128];

// ---------------------------------------------------------------------------
// f32x2 helpers
// ---------------------------------------------------------------------------
__device__ __forceinline__ unsigned long long pack2(float v) {
    unsigned long long r;
    asm("mov.b64 %0, {%1, %1};" : "=l"(r) : "f"(v));
    return r;
}
__device__ __forceinline__ void fma2(unsigned long long& d,
                                     unsigned long long a,
                                     unsigned long long b) {
    asm("fma.rn.f32x2 %0, %1, %2, %0;" : "+l"(d) : "l"(a), "l"(b));
}
__device__ __forceinline__ float2 unpack2(unsigned long long v) {
    float lo, hi;
    asm("mov.b64 {%0, %1}, %2;" : "=f"(lo), "=f"(hi) : "l"(v));
    return make_float2(lo, hi);
}

// ---------------------------------------------------------------------------
__global__ void zero_agg_kernel() {
    float4 z = make_float4(0.f, 0.f, 0.f, 0.f);
    float4* p = (float4*)g_agg;
    int n4 = NMAX * 32;
    for (int i = blockIdx.x * blockDim.x + threadIdx.x; i < n4;
         i += gridDim.x * blockDim.x)
        p[i] = z;
}
__global__ void zero_mol_kernel() {
    float4 z = make_float4(0.f, 0.f, 0.f, 0.f);
    float4* p = (float4*)g_mol;
    int n4 = MMAX * 32;
    for (int i = blockIdx.x * blockDim.x + threadIdx.x; i < n4;
         i += gridDim.x * blockDim.x)
        p[i] = z;
}

// ---------------------------------------------------------------------------
// Build the two 476x128 tables.
__global__ void table_kernel(const float* __restrict__ atom_table,
                             const float* __restrict__ bond_table,
                             const float* __restrict__ Wi,
                             const float* __restrict__ bi,
                             const float* __restrict__ Wu1,
                             const float* __restrict__ bu1) {
    int t = blockIdx.x >> 2;
    int a = blockIdx.x & 3;
    int j = threadIdx.x;

    __shared__ float sAtom[128];
    __shared__ float sBond[64];
    sAtom[j] = atom_table[t * 128 + j];
    if (j < 64) sBond[j] = bond_table[a * 64 + j];
    __syncthreads();

    float accI = bi[j];
    float accB = bu1[j];
#pragma unroll 8
    for (int k = 0; k < 128; k++) {
        float av = sAtom[k];
        accI = fmaf(av, Wi[k * 128 + j], accI);
        accB = fmaf(av, Wu1[k * 128 + j], accB);
    }
#pragma unroll 8
    for (int k = 0; k < 64; k++) {
        float bv = sBond[k];
        accI = fmaf(bv, Wi[(128 + k) * 128 + j], accI);
        accB = fmaf(bv, Wu1[(128 + k) * 128 + j], accB);
    }
    g_msgInit[blockIdx.x * 128 + j] = fmaxf(accI, 0.f);
    g_bias[blockIdx.x * 128 + j] = accB;
}

// ---------------------------------------------------------------------------
// Edge scatter: agg[dst] += table[row]; one warp per edge.
__global__ void scatter_kernel(const int* __restrict__ src,
                               const int* __restrict__ dst,
                               const int* __restrict__ attr,
                               const int* __restrict__ x,
                               int E, int useX) {
    const float* table = useX ? g_msgInit : g_msgTable;
    int lane = threadIdx.x & 31;
    int w = (blockIdx.x * blockDim.x + threadIdx.x) >> 5;
    int nw = (gridDim.x * blockDim.x) >> 5;
    for (int e = w; e < E; e += nw) {
        int s = src[e];
        int d = dst[e];
        int a = attr[e];
        int r = useX ? (x[s] * 4 + a) : (s * 4 + a);
        float4 v = ((const float4*)(table + (size_t)r * 128))[lane];
        float* out = g_agg + (size_t)d * 128 + lane * 4;
        asm volatile("red.global.add.v4.f32 [%0], {%1,%2,%3,%4};"
                     :: "l"(out), "f"(v.x), "f"(v.y), "f"(v.z), "f"(v.w)
                     : "memory");
    }
}

// ---------------------------------------------------------------------------
// 64x128 @ 128x128 GEMM on f32x2. Each thread: 4 rows x 4 cols.
// acc[r*2], acc[r*2+1] hold cols {lane*4, lane*4+1} and {lane*4+2, lane*4+3}.
__device__ __forceinline__ void gemm2_64x128(const float4* __restrict__ sA4,
                                             const ulonglong2* __restrict__ wp,
                                             int rbase, int lane,
                                             unsigned long long acc[8]) {
#pragma unroll
    for (int i = 0; i < 8; i++) acc[i] = 0ull;
#pragma unroll 4
    for (int k4 = 0; k4 < 32; k4++) {
        float a0[4], a1[4], a2[4], a3[4];
        *(float4*)a0 = sA4[(rbase + 0) * 32 + k4];
        *(float4*)a1 = sA4[(rbase + 1) * 32 + k4];
        *(float4*)a2 = sA4[(rbase + 2) * 32 + k4];
        *(float4*)a3 = sA4[(rbase + 3) * 32 + k4];
#pragma unroll
        for (int kk = 0; kk < 4; kk++) {
            ulonglong2 wv = wp[(k4 * 4 + kk) * 32 + lane];
            unsigned long long p0 = pack2(a0[kk]);
            unsigned long long p1 = pack2(a1[kk]);
            unsigned long long p2 = pack2(a2[kk]);
            unsigned long long p3 = pack2(a3[kk]);
            fma2(acc[0], p0, wv.x); fma2(acc[1], p0, wv.y);
            fma2(acc[2], p1, wv.x); fma2(acc[3], p1, wv.y);
            fma2(acc[4], p2, wv.x); fma2(acc[5], p2, wv.y);
            fma2(acc[6], p3, wv.x); fma2(acc[7], p3, wv.y);
        }
    }
}

// ---------------------------------------------------------------------------
// Update pass: 64 nodes/block, 512 threads.
// smem: sW1 (64KB Wu1agg), sW2 (64KB Wu2), sA (32KB activations) = 160KB.
__global__ void __launch_bounds__(512, 1)
update_kernel(const int* __restrict__ x,
              const float* __restrict__ Wu1agg,
              const float* __restrict__ Wu2,
              const float* __restrict__ bu2,
              int N) {
    extern __shared__ float smem[];
    float* sW1 = smem;
    float* sW2 = smem + 16384;
    float* sA = smem + 32768;
    __shared__ int sX[64];

    int tid = threadIdx.x;
    int lane = tid & 31;
    int w = tid >> 5;
    int rbase = w * 4;          // 16 warps * 4 rows = 64 rows
    int nb = blockIdx.x * 64;

    // Load both weight matrices + activations
    {
        const float4* w1s = (const float4*)Wu1agg;
        const float4* w2s = (const float4*)Wu2;
        float4* w1d = (float4*)sW1;
        float4* w2d = (float4*)sW2;
#pragma unroll
        for (int i = tid; i < 4096; i += 512) { w1d[i] = w1s[i]; w2d[i] = w2s[i]; }
        const float4* agg4 = (const float4*)g_agg;
        float4* sA4w = (float4*)sA;
#pragma unroll
        for (int i = tid; i < 2048; i += 512) {
            int row = i >> 5;
            sA4w[i] = (nb + row < N) ? agg4[(nb + row) * 32 + (i & 31)]
                                     : make_float4(0.f, 0.f, 0.f, 0.f);
        }
        if (tid < 64) sX[tid] = (nb + tid < N) ? x[nb + tid] * 4 : 0;
    }
    __syncthreads();

    const float4* sA4 = (const float4*)sA;
    float4* sA4w = (float4*)sA;
    const ulonglong2* wp1 = (const ulonglong2*)sW1;
    const ulonglong2* wp2 = (const ulonglong2*)sW2;
    const float4* bias4 = (const float4*)g_bias;
    float4 b2 = ((const float4*)bu2)[lane];
    float4* msg4 = (float4*)g_msgTable;

    // GEMM1: aggW = agg @ Wu1agg  (result stays in registers)
    unsigned long long accW[8];
    gemm2_64x128(sA4, wp1, rbase, lane, accW);
    __syncthreads();   // done reading sA; it becomes the h buffer

    for (int a = 0; a < 4; a++) {
        // h = relu(aggW + bias[x*4+a]) -> sA
#pragma unroll
        for (int r = 0; r < 4; r++) {
            float2 e0 = unpack2(accW[r * 2]);
            float2 e1 = unpack2(accW[r * 2 + 1]);
            float4 b = bias4[(size_t)(sX[rbase + r] + a) * 32 + lane];
            float4 h;
            h.x = fmaxf(e0.x + b.x, 0.f);
            h.y = fmaxf(e0.y + b.y, 0.f);
            h.z = fmaxf(e1.x + b.z, 0.f);
            h.w = fmaxf(e1.y + b.w, 0.f);
            sA4w[(rbase + r) * 32 + lane] = h;
        }
        __syncthreads();

        // msg = relu(h @ Wu2 + bu2)
        unsigned long long acc2[8];
        gemm2_64x128(sA4, wp2, rbase, lane, acc2);
#pragma unroll
        for (int r = 0; r < 4; r++) {
            int n = nb + rbase + r;
            if (n < N) {
                float2 e0 = unpack2(acc2[r * 2]);
                float2 e1 = unpack2(acc2[r * 2 + 1]);
                float4 o;
                o.x = fmaxf(e0.x + b2.x, 0.f);
                o.y = fmaxf(e0.y + b2.y, 0.f);
                o.z = fmaxf(e1.x + b2.z, 0.f);
                o.w = fmaxf(e1.y + b2.w, 0.f);
                msg4[((size_t)n * 4 + a) * 32 + lane] = o;
            }
        }
        __syncthreads();   // before next attr overwrites sA
    }
}

// ---------------------------------------------------------------------------
__global__ void mol_kernel(const int* __restrict__ batch, int N) {
    int lane = threadIdx.x & 31;
    int w = (blockIdx.x * blockDim.x + threadIdx.x) >> 5;
    int nw = (gridDim.x * blockDim.x) >> 5;
    const float4* ns4 = (const float4*)g_agg;
    for (int n = w; n < N; n += nw) {
        int m = batch[n];
        float4 v = ns4[n * 32 + lane];
        float* out = g_mol + (size_t)m * 128 + lane * 4;
        asm volatile("red.global.add.v4.f32 [%0], {%1,%2,%3,%4};"
                     :: "l"(out), "f"(v.x), "f"(v.y), "f"(v.z), "f"(v.w)
                     : "memory");
    }
}

// ---------------------------------------------------------------------------
__global__ void readout_kernel(const float* __restrict__ Wr1,
                               const float* __restrict__ br1,
                               const float* __restrict__ Wr2,
                               const float* __restrict__ br2,
                               float* __restrict__ out) {
    int m = blockIdx.x;
    int tid = threadIdx.x;  // 256
    __shared__ float sMol[128];
    __shared__ float sRed[8];
    if (tid < 128) sMol[tid] = g_mol[m * 128 + tid];
    __syncthreads();

    float part = 0.f;
#pragma unroll
    for (int jj = 0; jj < 2; jj++) {
        int j = tid + jj * 256;
        float h = br1[j];
#pragma unroll 8
        for (int k = 0; k < 128; k++)
            h = fmaf(sMol[k], Wr1[k * 512 + j], h);
        h = fmaxf(h, 0.f);
        part = fmaf(h, Wr2[j], part);
    }
#pragma unroll
    for (int off = 16; off; off >>= 1)
        part += __shfl_down_sync(0xffffffffu, part, off);
    if ((tid & 31) == 0) sRed[tid >> 5] = part;
    __syncthreads();
    if (tid == 0) {
        float s = br2[0];
#pragma unroll
        for (int i = 0; i < 8; i++) s += sRed[i];
        out[m] = s;
    }
}

// ---------------------------------------------------------------------------
#define SM_UPD 163840   // 160KB dynamic smem

extern "C" void kernel_launch(void* const* d_in, const int* in_sizes, int n_in,
                              void* d_out, int out_size) {
    const int*   x          = (const int*)d_in[0];
    const int*   eattr      = (const int*)d_in[1];
    const int*   eidx       = (const int*)d_in[2];
    const int*   batch      = (const int*)d_in[3];
    const float* atom_table = (const float*)d_in[4];
    const float* bond_table = (const float*)d_in[5];
    const float* Wi         = (const float*)d_in[6];
    const float* bi         = (const float*)d_in[7];
    const float* Wu1        = (const float*)d_in[8];
    const float* bu1        = (const float*)d_in[9];
    const float* Wu2        = (const float*)d_in[10];
    const float* bu2        = (const float*)d_in[11];
    const float* Wr1        = (const float*)d_in[12];
    const float* br1        = (const float*)d_in[13];
    const float* Wr2        = (const float*)d_in[14];
    const float* br2        = (const float*)d_in[15];
    float* out = (float*)d_out;

    int N = in_sizes[0];
    int E = in_sizes[1];
    int M = out_size;
    const int* src = eidx;
    const int* dst = eidx + E;

    cudaFuncSetAttribute(update_kernel,
                         cudaFuncAttributeMaxDynamicSharedMemorySize, SM_UPD);

    // Tables + initial scatter
    table_kernel<<<NTAB, 128>>>(atom_table, bond_table, Wi, bi, Wu1, bu1);
    zero_agg_kernel<<<1024, 256>>>();
    scatter_kernel<<<2048, 256>>>(src, dst, eattr, x, E, 1);

    int ublocks = (N + 63) / 64;
    for (int p = 0; p < 4; p++) {
        update_kernel<<<ublocks, 512, SM_UPD>>>(x, Wu1 + 192 * 128, Wu2, bu2, N);
        zero_agg_kernel<<<1024, 256>>>();
        scatter_kernel<<<2048, 256>>>(src, dst, eattr, x, E, 0);
    }

    zero_mol_kernel<<<64, 256>>>();
    mol_kernel<<<512, 256>>>(batch, N);
    readout_kernel<<<M, 256>>>(Wr1, br1, Wr2, br2, out);
}

// round 5
// speedup vs baseline: 1.4466x; 1.4389x over previous
#include <cuda_runtime.h>
#include <cuda_bf16.h>
#include <cstdint>

// ---------------------------------------------------------------------------
// BasicDMPNN on GB300 — round 5: mma.sync bf16x3 (hi/lo split) update GEMMs.
//   * tf32 single-word precision failed (3.4e-3); bf16 split gives ~2^-18/term
//   * 512 threads, 4m x 4n warps, 32x32 warp tiles, XOR-swizzled smem
//   * zero_agg folded into update kernel (zero-after-read)
// ---------------------------------------------------------------------------

#define NMAX 50000
#define MMAX 2000
#define NTAB 476

__device__ __align__(16) float g_bias[NTAB * 128];     // ab@Wu1[:192]+bu1
__device__ __align__(16) float g_msgInit[NTAB * 128];  // relu(ab@Wi+bi)
__device__ __align__(16) float g_agg[NMAX * 128];
__device__ __align__(16) float g_msgTable[NMAX * 4 * 128];
__device__ __align__(16) float g_mol[MMAX * 128];
__device__ __align__(16) uint4 g_Wf1[4096];            // Wu1agg frag image (hi/lo)
__device__ __align__(16) uint4 g_Wf2[4096];            // Wu2 frag image (hi/lo)

// ---------------------------------------------------------------------------
__device__ __forceinline__ uint32_t pack_bf16x2(float e0, float e1) {
    __nv_bfloat162 p = __floats2bfloat162_rn(e0, e1);  // x=e0 (low), y=e1 (high)
    return *reinterpret_cast<uint32_t*>(&p);
}
// split pair (e0,e1) into hi-pair and lo-pair bf16x2 words
__device__ __forceinline__ void split2(float e0, float e1,
                                       uint32_t& hi, uint32_t& lo) {
    float h0 = __bfloat162float(__float2bfloat16(e0));
    float h1 = __bfloat162float(__float2bfloat16(e1));
    hi = pack_bf16x2(h0, h1);
    lo = pack_bf16x2(e0 - h0, e1 - h1);
}

__device__ __forceinline__ void mma_bf16(float d[4], const uint32_t a[4],
                                         uint32_t b0, uint32_t b1) {
    asm volatile(
        "mma.sync.aligned.m16n8k16.row.col.f32.bf16.bf16.f32 "
        "{%0,%1,%2,%3}, {%4,%5,%6,%7}, {%8,%9}, {%0,%1,%2,%3};"
        : "+f"(d[0]), "+f"(d[1]), "+f"(d[2]), "+f"(d[3])
        : "r"(a[0]), "r"(a[1]), "r"(a[2]), "r"(a[3]), "r"(b0), "r"(b1));
}

// swizzled index into a 128-row x 64-pair activation array
__device__ __forceinline__ int aidx(int row, int kk) {
    return row * 64 + (kk ^ ((row & 7) << 2));
}

// ---------------------------------------------------------------------------
__global__ void zero_agg_kernel() {
    float4 z = make_float4(0.f, 0.f, 0.f, 0.f);
    float4* p = (float4*)g_agg;
    int n4 = NMAX * 32;
    for (int i = blockIdx.x * blockDim.x + threadIdx.x; i < n4;
         i += gridDim.x * blockDim.x)
        p[i] = z;
}
__global__ void zero_mol_kernel() {
    float4 z = make_float4(0.f, 0.f, 0.f, 0.f);
    float4* p = (float4*)g_mol;
    int n4 = MMAX * 32;
    for (int i = blockIdx.x * blockDim.x + threadIdx.x; i < n4;
         i += gridDim.x * blockDim.x)
        p[i] = z;
}

// ---------------------------------------------------------------------------
// Build the two 476x128 tables (exact fp32).
__global__ void table_kernel(const float* __restrict__ atom_table,
                             const float* __restrict__ bond_table,
                             const float* __restrict__ Wi,
                             const float* __restrict__ bi,
                             const float* __restrict__ Wu1,
                             const float* __restrict__ bu1) {
    int t = blockIdx.x >> 2;
    int a = blockIdx.x & 3;
    int j = threadIdx.x;

    __shared__ float sAtom[128];
    __shared__ float sBond[64];
    sAtom[j] = atom_table[t * 128 + j];
    if (j < 64) sBond[j] = bond_table[a * 64 + j];
    __syncthreads();

    float accI = bi[j];
    float accB = bu1[j];
#pragma unroll 8
    for (int k = 0; k < 128; k++) {
        float av = sAtom[k];
        accI = fmaf(av, Wi[k * 128 + j], accI);
        accB = fmaf(av, Wu1[k * 128 + j], accB);
    }
#pragma unroll 8
    for (int k = 0; k < 64; k++) {
        float bv = sBond[k];
        accI = fmaf(bv, Wi[(128 + k) * 128 + j], accI);
        accB = fmaf(bv, Wu1[(128 + k) * 128 + j], accB);
    }
    g_msgInit[blockIdx.x * 128 + j] = fmaxf(accI, 0.f);
    g_bias[blockIdx.x * 128 + j] = accB;
}

// ---------------------------------------------------------------------------
// Pack W (k-major [128,128]) into fragment-ordered bf16 hi/lo images.
// entry i = (ks*16 + ntile)*32 + lane; b0 pairs k0=ks*16+(lane&3)*2, b1 k0+8;
// n = ntile*8 + (lane>>2). uint4 = {b0hi, b1hi, b0lo, b1lo}.
__global__ void prep_wfrag_kernel(const float* __restrict__ W1,
                                  const float* __restrict__ W2) {
    int i = blockIdx.x * blockDim.x + threadIdx.x;
    if (i >= 4096) return;
    int lane = i & 31;
    int ntile = (i >> 5) & 15;
    int ks = i >> 9;
    int k0 = ks * 16 + (lane & 3) * 2;
    int n = ntile * 8 + (lane >> 2);

    const float* Ws[2] = {W1, W2};
    uint4* imgs[2] = {g_Wf1, g_Wf2};
#pragma unroll
    for (int m = 0; m < 2; m++) {
        const float* W = Ws[m];
        uint4 v;
        split2(W[k0 * 128 + n], W[(k0 + 1) * 128 + n], v.x, v.z);
        split2(W[(k0 + 8) * 128 + n], W[(k0 + 9) * 128 + n], v.y, v.w);
        imgs[m][i] = v;
    }
}

// ---------------------------------------------------------------------------
// Edge scatter: agg[dst] += table[row]; one warp per edge.
__global__ void scatter_kernel(const int* __restrict__ src,
                               const int* __restrict__ dst,
                               const int* __restrict__ attr,
                               const int* __restrict__ x,
                               int E, int useX) {
    const float* table = useX ? g_msgInit : g_msgTable;
    int lane = threadIdx.x & 31;
    int w = (blockIdx.x * blockDim.x + threadIdx.x) >> 5;
    int nw = (gridDim.x * blockDim.x) >> 5;
    for (int e = w; e < E; e += nw) {
        int s = src[e];
        int d = dst[e];
        int a = attr[e];
        int r = useX ? (x[s] * 4 + a) : (s * 4 + a);
        float4 v = ((const float4*)(table + (size_t)r * 128))[lane];
        float* out = g_agg + (size_t)d * 128 + lane * 4;
        asm volatile("red.global.add.v4.f32 [%0], {%1,%2,%3,%4};"
                     :: "l"(out), "f"(v.x), "f"(v.y), "f"(v.z), "f"(v.w)
                     : "memory");
    }
}

// ---------------------------------------------------------------------------
// 128x128 @ 128x128 bf16x3 GEMM. Warp (wm 0..3, wn 0..3): 32 rows x 32 cols.
__device__ __forceinline__ void gemm_bf16x3(const uint32_t* __restrict__ sAhi,
                                            const uint32_t* __restrict__ sAlo,
                                            const uint4* __restrict__ sW,
                                            int wm, int wn, int lane,
                                            float D[2][4][4]) {
#pragma unroll
    for (int mt = 0; mt < 2; mt++)
#pragma unroll
        for (int nt = 0; nt < 4; nt++)
#pragma unroll
            for (int q = 0; q < 4; q++) D[mt][nt][q] = 0.f;

#pragma unroll
    for (int ks = 0; ks < 8; ks++) {
        uint32_t Ahi[2][4], Alo[2][4];
#pragma unroll
        for (int mt = 0; mt < 2; mt++) {
            int r = wm * 32 + mt * 16 + (lane >> 2);
            int kk = ks * 8 + (lane & 3);
            Ahi[mt][0] = sAhi[aidx(r, kk)];
            Ahi[mt][1] = sAhi[aidx(r + 8, kk)];
            Ahi[mt][2] = sAhi[aidx(r, kk + 4)];
            Ahi[mt][3] = sAhi[aidx(r + 8, kk + 4)];
            Alo[mt][0] = sAlo[aidx(r, kk)];
            Alo[mt][1] = sAlo[aidx(r + 8, kk)];
            Alo[mt][2] = sAlo[aidx(r, kk + 4)];
            Alo[mt][3] = sAlo[aidx(r + 8, kk + 4)];
        }
#pragma unroll
        for (int nt = 0; nt < 4; nt++) {
            uint4 B = sW[(ks * 16 + wn * 4 + nt) * 32 + lane];
            mma_bf16(D[0][nt], Ahi[0], B.x, B.y);   // hi*hi
            mma_bf16(D[1][nt], Ahi[1], B.x, B.y);
            mma_bf16(D[0][nt], Ahi[0], B.z, B.w);   // hi*lo
            mma_bf16(D[1][nt], Ahi[1], B.z, B.w);
            mma_bf16(D[0][nt], Alo[0], B.x, B.y);   // lo*hi
            mma_bf16(D[1][nt], Alo[1], B.x, B.y);
        }
    }
}

// ---------------------------------------------------------------------------
// Update pass: 128 nodes/block, 512 threads.
// smem: sAhi 32KB + sAlo 32KB + W1 64KB + W2 64KB = 192KB.
#define SM_UPD (32768 + 32768 + 65536 + 65536)

__global__ void __launch_bounds__(512, 1)
update_mma_kernel(const int* __restrict__ x, const float* __restrict__ bu2, int N) {
    extern __shared__ uint32_t smem[];
    uint32_t* sAhi = smem;
    uint32_t* sAlo = smem + 8192;
    uint4* sW1 = (uint4*)(smem + 16384);
    uint4* sW2 = sW1 + 4096;
    __shared__ int sX[128];

    int tid = threadIdx.x;
    int lane = tid & 31;
    int wid = tid >> 5;
    int wm = wid >> 2;     // 0..3
    int wn = wid & 3;      // 0..3
    int nb = blockIdx.x * 128;

    // Weight frag images -> smem
    {
#pragma unroll
        for (int i = tid; i < 4096; i += 512) { sW1[i] = g_Wf1[i]; sW2[i] = g_Wf2[i]; }
    }
    // agg -> split bf16 -> sA; zero g_agg after read (replaces zero kernel)
    {
        float4* agg4 = (float4*)g_agg;
#pragma unroll
        for (int i = tid; i < 4096; i += 512) {
            int row = i >> 5;
            int q = i & 31;
            float4 v = make_float4(0.f, 0.f, 0.f, 0.f);
            if (nb + row < N) {
                v = agg4[(size_t)(nb + row) * 32 + q];
                agg4[(size_t)(nb + row) * 32 + q] = make_float4(0.f, 0.f, 0.f, 0.f);
            }
            uint32_t h0, l0, h1, l1;
            split2(v.x, v.y, h0, l0);
            split2(v.z, v.w, h1, l1);
            int p = aidx(row, 2 * q);     // swizzle keeps bit0, p+1 valid
            sAhi[p] = h0; sAhi[p + 1] = h1;
            sAlo[p] = l0; sAlo[p + 1] = l1;
        }
        if (tid < 128) sX[tid] = (nb + tid < N) ? x[nb + tid] * 4 : 0;
    }
    __syncthreads();

    // GEMM1: D1 = agg @ Wu1agg (registers)
    float D1[2][4][4];
    gemm_bf16x3(sAhi, sAlo, sW1, wm, wn, lane, D1);
    __syncthreads();

    // bu2 per-thread columns
    float2 b2v[4];
#pragma unroll
    for (int nt = 0; nt < 4; nt++)
        b2v[nt] = *(const float2*)(bu2 + (wn * 4 + nt) * 8 + (lane & 3) * 2);

    int r0 = wm * 32 + (lane >> 2);
    int c0 = (lane & 3) * 2;

    for (int a = 0; a < 4; a++) {
        // h = relu(D1 + bias[x*4+a]) -> split -> sA
#pragma unroll
        for (int mt = 0; mt < 2; mt++) {
#pragma unroll
            for (int hh = 0; hh < 2; hh++) {
                int r = r0 + mt * 16 + hh * 8;
                const float* bp = g_bias + (size_t)(sX[r] + a) * 128;
#pragma unroll
                for (int nt = 0; nt < 4; nt++) {
                    int col = (wn * 4 + nt) * 8 + c0;
                    float2 b = *(const float2*)(bp + col);
                    float h0 = fmaxf(D1[mt][nt][hh * 2] + b.x, 0.f);
                    float h1 = fmaxf(D1[mt][nt][hh * 2 + 1] + b.y, 0.f);
                    uint32_t ph, pl;
                    split2(h0, h1, ph, pl);
                    int p = aidx(r, col >> 1);
                    sAhi[p] = ph;
                    sAlo[p] = pl;
                }
            }
        }
        __syncthreads();

        // GEMM2: D2 = h @ Wu2
        float D2[2][4][4];
        gemm_bf16x3(sAhi, sAlo, sW2, wm, wn, lane, D2);

        // msg = relu(D2 + bu2) -> g_msgTable
#pragma unroll
        for (int mt = 0; mt < 2; mt++) {
#pragma unroll
            for (int hh = 0; hh < 2; hh++) {
                int r = r0 + mt * 16 + hh * 8;
                int n = nb + r;
                if (n < N) {
                    float* mp = g_msgTable + ((size_t)n * 4 + a) * 128;
#pragma unroll
                    for (int nt = 0; nt < 4; nt++) {
                        int col = (wn * 4 + nt) * 8 + c0;
                        float2 o;
                        o.x = fmaxf(D2[mt][nt][hh * 2] + b2v[nt].x, 0.f);
                        o.y = fmaxf(D2[mt][nt][hh * 2 + 1] + b2v[nt].y, 0.f);
                        *(float2*)(mp + col) = o;
                    }
                }
            }
        }
        __syncthreads();   // before next attr overwrites sA
    }
}

// ---------------------------------------------------------------------------
__global__ void mol_kernel(const int* __restrict__ batch, int N) {
    int lane = threadIdx.x & 31;
    int w = (blockIdx.x * blockDim.x + threadIdx.x) >> 5;
    int nw = (gridDim.x * blockDim.x) >> 5;
    const float4* ns4 = (const float4*)g_agg;
    for (int n = w; n < N; n += nw) {
        int m = batch[n];
        float4 v = ns4[n * 32 + lane];
        float* out = g_mol + (size_t)m * 128 + lane * 4;
        asm volatile("red.global.add.v4.f32 [%0], {%1,%2,%3,%4};"
                     :: "l"(out), "f"(v.x), "f"(v.y), "f"(v.z), "f"(v.w)
                     : "memory");
    }
}

// ---------------------------------------------------------------------------
__global__ void readout_kernel(const float* __restrict__ Wr1,
                               const float* __restrict__ br1,
                               const float* __restrict__ Wr2,
                               const float* __restrict__ br2,
                               float* __restrict__ out) {
    int m = blockIdx.x;
    int tid = threadIdx.x;  // 256
    __shared__ float sMol[128];
    __shared__ float sRed[8];
    if (tid < 128) sMol[tid] = g_mol[m * 128 + tid];
    __syncthreads();

    float part = 0.f;
#pragma unroll
    for (int jj = 0; jj < 2; jj++) {
        int j = tid + jj * 256;
        float h = br1[j];
#pragma unroll 8
        for (int k = 0; k < 128; k++)
            h = fmaf(sMol[k], Wr1[k * 512 + j], h);
        h = fmaxf(h, 0.f);
        part = fmaf(h, Wr2[j], part);
    }
#pragma unroll
    for (int off = 16; off; off >>= 1)
        part += __shfl_down_sync(0xffffffffu, part, off);
    if ((tid & 31) == 0) sRed[tid >> 5] = part;
    __syncthreads();
    if (tid == 0) {
        float s = br2[0];
#pragma unroll
        for (int i = 0; i < 8; i++) s += sRed[i];
        out[m] = s;
    }
}

// ---------------------------------------------------------------------------
extern "C" void kernel_launch(void* const* d_in, const int* in_sizes, int n_in,
                              void* d_out, int out_size) {
    const int*   x          = (const int*)d_in[0];
    const int*   eattr      = (const int*)d_in[1];
    const int*   eidx       = (const int*)d_in[2];
    const int*   batch      = (const int*)d_in[3];
    const float* atom_table = (const float*)d_in[4];
    const float* bond_table = (const float*)d_in[5];
    const float* Wi         = (const float*)d_in[6];
    const float* bi         = (const float*)d_in[7];
    const float* Wu1        = (const float*)d_in[8];
    const float* bu1        = (const float*)d_in[9];
    const float* Wu2        = (const float*)d_in[10];
    const float* bu2        = (const float*)d_in[11];
    const float* Wr1        = (const float*)d_in[12];
    const float* br1        = (const float*)d_in[13];
    const float* Wr2        = (const float*)d_in[14];
    const float* br2        = (const float*)d_in[15];
    float* out = (float*)d_out;

    int N = in_sizes[0];
    int E = in_sizes[1];
    int M = out_size;
    const int* src = eidx;
    const int* dst = eidx + E;

    cudaFuncSetAttribute(update_mma_kernel,
                         cudaFuncAttributeMaxDynamicSharedMemorySize, SM_UPD);

    // Tables + weight frag images + initial scatter
    table_kernel<<<NTAB, 128>>>(atom_table, bond_table, Wi, bi, Wu1, bu1);
    prep_wfrag_kernel<<<16, 256>>>(Wu1 + 192 * 128, Wu2);
    zero_agg_kernel<<<1024, 256>>>();
    scatter_kernel<<<2048, 256>>>(src, dst, eattr, x, E, 1);

    int ublocks = (N + 127) / 128;
    for (int p = 0; p < 4; p++) {
        update_mma_kernel<<<ublocks, 512, SM_UPD>>>(x, bu2, N);   // zeroes g_agg
        scatter_kernel<<<2048, 256>>>(src, dst, eattr, x, E, 0);
    }

    zero_mol_kernel<<<64, 256>>>();
    mol_kernel<<<512, 256>>>(batch, N);
    readout_kernel<<<M, 256>>>(Wr1, br1, Wr2, br2, out);
}

// round 7
// speedup vs baseline: 1.9374x; 1.3393x over previous
#include <cuda_runtime.h>
#include <cuda_bf16.h>
#include <cstdint>

// ---------------------------------------------------------------------------
// BasicDMPNN on GB300 — round 7: CSR gather-reduce (round-6 fix: device-global
// pointers resolved IN-KERNEL via flag, never passed from host).
//   * CSR of in-edges built once per launch (hist -> scan -> fill)
//   * aggregation: warp-per-node register reduce, single 512B store, no atomics
//   * update GEMMs: mma.sync bf16x3 (round-5 winner, unchanged math)
// ---------------------------------------------------------------------------

#define NMAX 50000
#define EMAX 800000
#define MMAX 2000
#define NTAB 476

__device__ __align__(16) float g_bias[NTAB * 128];     // ab@Wu1[:192]+bu1
__device__ __align__(16) float g_msgInit[NTAB * 128];  // relu(ab@Wi+bi)
__device__ __align__(16) float g_agg[NMAX * 128];
__device__ __align__(16) float g_msgTable[NMAX * 4 * 128];
__device__ __align__(16) float g_mol[MMAX * 128];
__device__ __align__(16) uint4 g_Wf1[4096];            // Wu1agg frag image (hi/lo)
__device__ __align__(16) uint4 g_Wf2[4096];            // Wu2 frag image (hi/lo)

// CSR scratch
__device__ int g_hist[NMAX];
__device__ int g_rowStart[NMAX + 1];
__device__ int g_cursor[NMAX];
__device__ int g_row0[EMAX];   // x[src]*4+attr  (init-message row ids)
__device__ int g_rowU[EMAX];   // src*4+attr     (update-message row ids)

// ---------------------------------------------------------------------------
__device__ __forceinline__ uint32_t pack_bf16x2(float e0, float e1) {
    __nv_bfloat162 p = __floats2bfloat162_rn(e0, e1);
    return *reinterpret_cast<uint32_t*>(&p);
}
__device__ __forceinline__ void split2(float e0, float e1,
                                       uint32_t& hi, uint32_t& lo) {
    float h0 = __bfloat162float(__float2bfloat16(e0));
    float h1 = __bfloat162float(__float2bfloat16(e1));
    hi = pack_bf16x2(h0, h1);
    lo = pack_bf16x2(e0 - h0, e1 - h1);
}
__device__ __forceinline__ void mma_bf16(float d[4], const uint32_t a[4],
                                         uint32_t b0, uint32_t b1) {
    asm volatile(
        "mma.sync.aligned.m16n8k16.row.col.f32.bf16.bf16.f32 "
        "{%0,%1,%2,%3}, {%4,%5,%6,%7}, {%8,%9}, {%0,%1,%2,%3};"
        : "+f"(d[0]), "+f"(d[1]), "+f"(d[2]), "+f"(d[3])
        : "r"(a[0]), "r"(a[1]), "r"(a[2]), "r"(a[3]), "r"(b0), "r"(b1));
}
__device__ __forceinline__ int aidx(int row, int kk) {
    return row * 64 + (kk ^ ((row & 7) << 2));
}

// ---------------------------------------------------------------------------
// CSR build
// ---------------------------------------------------------------------------
__global__ void csr_zero_kernel(int N) {
    for (int i = blockIdx.x * blockDim.x + threadIdx.x; i < N;
         i += gridDim.x * blockDim.x)
        g_hist[i] = 0;
}
__global__ void csr_count_kernel(const int* __restrict__ dst, int E) {
    for (int e = blockIdx.x * blockDim.x + threadIdx.x; e < E;
         e += gridDim.x * blockDim.x)
        atomicAdd(&g_hist[dst[e]], 1);
}
__global__ void __launch_bounds__(1024, 1) csr_scan_kernel(int N) {
    __shared__ int part[1024];
    int tid = threadIdx.x;
    int per = (N + 1023) / 1024;
    int start = tid * per;
    int sum = 0;
    for (int i = 0; i < per; i++) {
        int idx = start + i;
        if (idx < N) sum += g_hist[idx];
    }
    part[tid] = sum;
    __syncthreads();
    for (int off = 1; off < 1024; off <<= 1) {
        int v = (tid >= off) ? part[tid - off] : 0;
        __syncthreads();
        part[tid] += v;
        __syncthreads();
    }
    int run = tid ? part[tid - 1] : 0;
    for (int i = 0; i < per; i++) {
        int idx = start + i;
        if (idx < N) {
            g_rowStart[idx] = run;
            g_cursor[idx] = run;
            run += g_hist[idx];
        }
    }
    if (tid == 1023) g_rowStart[N] = part[1023];
}
__global__ void csr_fill_kernel(const int* __restrict__ src,
                                const int* __restrict__ dst,
                                const int* __restrict__ attr,
                                const int* __restrict__ x, int E) {
    for (int e = blockIdx.x * blockDim.x + threadIdx.x; e < E;
         e += gridDim.x * blockDim.x) {
        int d = dst[e];
        int s = src[e];
        int a = attr[e];
        int pos = atomicAdd(&g_cursor[d], 1);
        g_rowU[pos] = s * 4 + a;
        g_row0[pos] = x[s] * 4 + a;
    }
}

// ---------------------------------------------------------------------------
// Aggregation: warp per node, register reduce, one plain store. No atomics.
// useInit=1: rowids=g_row0, table=g_msgInit; else g_rowU / g_msgTable.
// (Device globals referenced in-kernel only — host cannot pass their address.)
__global__ void gather_agg_kernel(int useInit, int N) {
    const int* __restrict__ rowids = useInit ? g_row0 : g_rowU;
    const float* __restrict__ table = useInit ? g_msgInit : g_msgTable;
    int lane = threadIdx.x & 31;
    int w = (blockIdx.x * blockDim.x + threadIdx.x) >> 5;
    int nw = (gridDim.x * blockDim.x) >> 5;
    for (int n = w; n < N; n += nw) {
        int s0 = g_rowStart[n];
        int s1 = g_rowStart[n + 1];
        float4 acc = make_float4(0.f, 0.f, 0.f, 0.f);
        int j = s0;
        for (; j + 2 <= s1; j += 2) {
            int r0 = __ldg(rowids + j);
            int r1 = __ldg(rowids + j + 1);
            float4 v0 = ((const float4*)(table + (size_t)r0 * 128))[lane];
            float4 v1 = ((const float4*)(table + (size_t)r1 * 128))[lane];
            acc.x += v0.x; acc.y += v0.y; acc.z += v0.z; acc.w += v0.w;
            acc.x += v1.x; acc.y += v1.y; acc.z += v1.z; acc.w += v1.w;
        }
        if (j < s1) {
            int r0 = __ldg(rowids + j);
            float4 v0 = ((const float4*)(table + (size_t)r0 * 128))[lane];
            acc.x += v0.x; acc.y += v0.y; acc.z += v0.z; acc.w += v0.w;
        }
        ((float4*)(g_agg + (size_t)n * 128))[lane] = acc;
    }
}

// ---------------------------------------------------------------------------
// Build the two 476x128 tables (exact fp32).
__global__ void table_kernel(const float* __restrict__ atom_table,
                             const float* __restrict__ bond_table,
                             const float* __restrict__ Wi,
                             const float* __restrict__ bi,
                             const float* __restrict__ Wu1,
                             const float* __restrict__ bu1) {
    int t = blockIdx.x >> 2;
    int a = blockIdx.x & 3;
    int j = threadIdx.x;

    __shared__ float sAtom[128];
    __shared__ float sBond[64];
    sAtom[j] = atom_table[t * 128 + j];
    if (j < 64) sBond[j] = bond_table[a * 64 + j];
    __syncthreads();

    float accI = bi[j];
    float accB = bu1[j];
#pragma unroll 8
    for (int k = 0; k < 128; k++) {
        float av = sAtom[k];
        accI = fmaf(av, Wi[k * 128 + j], accI);
        accB = fmaf(av, Wu1[k * 128 + j], accB);
    }
#pragma unroll 8
    for (int k = 0; k < 64; k++) {
        float bv = sBond[k];
        accI = fmaf(bv, Wi[(128 + k) * 128 + j], accI);
        accB = fmaf(bv, Wu1[(128 + k) * 128 + j], accB);
    }
    g_msgInit[blockIdx.x * 128 + j] = fmaxf(accI, 0.f);
    g_bias[blockIdx.x * 128 + j] = accB;
}

// ---------------------------------------------------------------------------
// Pack W (k-major [128,128]) into fragment-ordered bf16 hi/lo images.
__global__ void prep_wfrag_kernel(const float* __restrict__ W1,
                                  const float* __restrict__ W2) {
    int i = blockIdx.x * blockDim.x + threadIdx.x;
    if (i >= 4096) return;
    int lane = i & 31;
    int ntile = (i >> 5) & 15;
    int ks = i >> 9;
    int k0 = ks * 16 + (lane & 3) * 2;
    int n = ntile * 8 + (lane >> 2);

    const float* Ws[2] = {W1, W2};
    uint4* imgs[2] = {g_Wf1, g_Wf2};
#pragma unroll
    for (int m = 0; m < 2; m++) {
        const float* W = Ws[m];
        uint4 v;
        split2(W[k0 * 128 + n], W[(k0 + 1) * 128 + n], v.x, v.z);
        split2(W[(k0 + 8) * 128 + n], W[(k0 + 9) * 128 + n], v.y, v.w);
        imgs[m][i] = v;
    }
}

// ---------------------------------------------------------------------------
// 128x128 @ 128x128 bf16x3 GEMM. Warp (wm 0..3, wn 0..3): 32 rows x 32 cols.
__device__ __forceinline__ void gemm_bf16x3(const uint32_t* __restrict__ sAhi,
                                            const uint32_t* __restrict__ sAlo,
                                            const uint4* __restrict__ sW,
                                            int wm, int wn, int lane,
                                            float D[2][4][4]) {
#pragma unroll
    for (int mt = 0; mt < 2; mt++)
#pragma unroll
        for (int nt = 0; nt < 4; nt++)
#pragma unroll
            for (int q = 0; q < 4; q++) D[mt][nt][q] = 0.f;

#pragma unroll
    for (int ks = 0; ks < 8; ks++) {
        uint32_t Ahi[2][4], Alo[2][4];
#pragma unroll
        for (int mt = 0; mt < 2; mt++) {
            int r = wm * 32 + mt * 16 + (lane >> 2);
            int kk = ks * 8 + (lane & 3);
            Ahi[mt][0] = sAhi[aidx(r, kk)];
            Ahi[mt][1] = sAhi[aidx(r + 8, kk)];
            Ahi[mt][2] = sAhi[aidx(r, kk + 4)];
            Ahi[mt][3] = sAhi[aidx(r + 8, kk + 4)];
            Alo[mt][0] = sAlo[aidx(r, kk)];
            Alo[mt][1] = sAlo[aidx(r + 8, kk)];
            Alo[mt][2] = sAlo[aidx(r, kk + 4)];
            Alo[mt][3] = sAlo[aidx(r + 8, kk + 4)];
        }
#pragma unroll
        for (int nt = 0; nt < 4; nt++) {
            uint4 B = sW[(ks * 16 + wn * 4 + nt) * 32 + lane];
            mma_bf16(D[0][nt], Ahi[0], B.x, B.y);   // hi*hi
            mma_bf16(D[1][nt], Ahi[1], B.x, B.y);
            mma_bf16(D[0][nt], Ahi[0], B.z, B.w);   // hi*lo
            mma_bf16(D[1][nt], Ahi[1], B.z, B.w);
            mma_bf16(D[0][nt], Alo[0], B.x, B.y);   // lo*hi
            mma_bf16(D[1][nt], Alo[1], B.x, B.y);
        }
    }
}

// ---------------------------------------------------------------------------
// Update pass: 128 nodes/block, 512 threads.
#define SM_UPD (32768 + 32768 + 65536 + 65536)

__global__ void __launch_bounds__(512, 1)
update_mma_kernel(const int* __restrict__ x, const float* __restrict__ bu2, int N) {
    extern __shared__ uint32_t smem[];
    uint32_t* sAhi = smem;
    uint32_t* sAlo = smem + 8192;
    uint4* sW1 = (uint4*)(smem + 16384);
    uint4* sW2 = sW1 + 4096;
    __shared__ int sX[128];

    int tid = threadIdx.x;
    int lane = tid & 31;
    int wid = tid >> 5;
    int wm = wid >> 2;
    int wn = wid & 3;
    int nb = blockIdx.x * 128;

#pragma unroll
    for (int i = tid; i < 4096; i += 512) { sW1[i] = g_Wf1[i]; sW2[i] = g_Wf2[i]; }
    {
        const float4* agg4 = (const float4*)g_agg;
#pragma unroll
        for (int i = tid; i < 4096; i += 512) {
            int row = i >> 5;
            int q = i & 31;
            float4 v = (nb + row < N) ? agg4[(size_t)(nb + row) * 32 + q]
                                      : make_float4(0.f, 0.f, 0.f, 0.f);
            uint32_t h0, l0, h1, l1;
            split2(v.x, v.y, h0, l0);
            split2(v.z, v.w, h1, l1);
            int p = aidx(row, 2 * q);
            sAhi[p] = h0; sAhi[p + 1] = h1;
            sAlo[p] = l0; sAlo[p + 1] = l1;
        }
        if (tid < 128) sX[tid] = (nb + tid < N) ? x[nb + tid] * 4 : 0;
    }
    __syncthreads();

    float D1[2][4][4];
    gemm_bf16x3(sAhi, sAlo, sW1, wm, wn, lane, D1);
    __syncthreads();

    float2 b2v[4];
#pragma unroll
    for (int nt = 0; nt < 4; nt++)
        b2v[nt] = *(const float2*)(bu2 + (wn * 4 + nt) * 8 + (lane & 3) * 2);

    int r0 = wm * 32 + (lane >> 2);
    int c0 = (lane & 3) * 2;

    for (int a = 0; a < 4; a++) {
#pragma unroll
        for (int mt = 0; mt < 2; mt++) {
#pragma unroll
            for (int hh = 0; hh < 2; hh++) {
                int r = r0 + mt * 16 + hh * 8;
                const float* bp = g_bias + (size_t)(sX[r] + a) * 128;
#pragma unroll
                for (int nt = 0; nt < 4; nt++) {
                    int col = (wn * 4 + nt) * 8 + c0;
                    float2 b = *(const float2*)(bp + col);
                    float h0 = fmaxf(D1[mt][nt][hh * 2] + b.x, 0.f);
                    float h1 = fmaxf(D1[mt][nt][hh * 2 + 1] + b.y, 0.f);
                    uint32_t ph, pl;
                    split2(h0, h1, ph, pl);
                    int p = aidx(r, col >> 1);
                    sAhi[p] = ph;
                    sAlo[p] = pl;
                }
            }
        }
        __syncthreads();

        float D2[2][4][4];
        gemm_bf16x3(sAhi, sAlo, sW2, wm, wn, lane, D2);

#pragma unroll
        for (int mt = 0; mt < 2; mt++) {
#pragma unroll
            for (int hh = 0; hh < 2; hh++) {
                int r = r0 + mt * 16 + hh * 8;
                int n = nb + r;
                if (n < N) {
                    float* mp = g_msgTable + ((size_t)n * 4 + a) * 128;
#pragma unroll
                    for (int nt = 0; nt < 4; nt++) {
                        int col = (wn * 4 + nt) * 8 + c0;
                        float2 o;
                        o.x = fmaxf(D2[mt][nt][hh * 2] + b2v[nt].x, 0.f);
                        o.y = fmaxf(D2[mt][nt][hh * 2 + 1] + b2v[nt].y, 0.f);
                        *(float2*)(mp + col) = o;
                    }
                }
            }
        }
        __syncthreads();
    }
}

// ---------------------------------------------------------------------------
__global__ void zero_mol_kernel() {
    float4 z = make_float4(0.f, 0.f, 0.f, 0.f);
    float4* p = (float4*)g_mol;
    int n4 = MMAX * 32;
    for (int i = blockIdx.x * blockDim.x + threadIdx.x; i < n4;
         i += gridDim.x * blockDim.x)
        p[i] = z;
}
__global__ void mol_kernel(const int* __restrict__ batch, int N) {
    int lane = threadIdx.x & 31;
    int w = (blockIdx.x * blockDim.x + threadIdx.x) >> 5;
    int nw = (gridDim.x * blockDim.x) >> 5;
    const float4* ns4 = (const float4*)g_agg;
    for (int n = w; n < N; n += nw) {
        int m = batch[n];
        float4 v = ns4[n * 32 + lane];
        float* out = g_mol + (size_t)m * 128 + lane * 4;
        asm volatile("red.global.add.v4.f32 [%0], {%1,%2,%3,%4};"
                     :: "l"(out), "f"(v.x), "f"(v.y), "f"(v.z), "f"(v.w)
                     : "memory");
    }
}

// ---------------------------------------------------------------------------
__global__ void readout_kernel(const float* __restrict__ Wr1,
                               const float* __restrict__ br1,
                               const float* __restrict__ Wr2,
                               const float* __restrict__ br2,
                               float* __restrict__ out) {
    int m = blockIdx.x;
    int tid = threadIdx.x;  // 256
    __shared__ float sMol[128];
    __shared__ float sRed[8];
    if (tid < 128) sMol[tid] = g_mol[m * 128 + tid];
    __syncthreads();

    float part = 0.f;
#pragma unroll
    for (int jj = 0; jj < 2; jj++) {
        int j = tid + jj * 256;
        float h = br1[j];
#pragma unroll 8
        for (int k = 0; k < 128; k++)
            h = fmaf(sMol[k], Wr1[k * 512 + j], h);
        h = fmaxf(h, 0.f);
        part = fmaf(h, Wr2[j], part);
    }
#pragma unroll
    for (int off = 16; off; off >>= 1)
        part += __shfl_down_sync(0xffffffffu, part, off);
    if ((tid & 31) == 0) sRed[tid >> 5] = part;
    __syncthreads();
    if (tid == 0) {
        float s = br2[0];
#pragma unroll
        for (int i = 0; i < 8; i++) s += sRed[i];
        out[m] = s;
    }
}

// ---------------------------------------------------------------------------
extern "C" void kernel_launch(void* const* d_in, const int* in_sizes, int n_in,
                              void* d_out, int out_size) {
    const int*   x          = (const int*)d_in[0];
    const int*   eattr      = (const int*)d_in[1];
    const int*   eidx       = (const int*)d_in[2];
    const int*   batch      = (const int*)d_in[3];
    const float* atom_table = (const float*)d_in[4];
    const float* bond_table = (const float*)d_in[5];
    const float* Wi         = (const float*)d_in[6];
    const float* bi         = (const float*)d_in[7];
    const float* Wu1        = (const float*)d_in[8];
    const float* bu1        = (const float*)d_in[9];
    const float* Wu2        = (const float*)d_in[10];
    const float* bu2        = (const float*)d_in[11];
    const float* Wr1        = (const float*)d_in[12];
    const float* br1        = (const float*)d_in[13];
    const float* Wr2        = (const float*)d_in[14];
    const float* br2        = (const float*)d_in[15];
    float* out = (float*)d_out;

    int N = in_sizes[0];
    int E = in_sizes[1];
    int M = out_size;
    const int* src = eidx;
    const int* dst = eidx + E;

    cudaFuncSetAttribute(update_mma_kernel,
                         cudaFuncAttributeMaxDynamicSharedMemorySize, SM_UPD);

    // Tables + weight frag images + CSR build
    table_kernel<<<NTAB, 128>>>(atom_table, bond_table, Wi, bi, Wu1, bu1);
    prep_wfrag_kernel<<<16, 256>>>(Wu1 + 192 * 128, Wu2);
    csr_zero_kernel<<<128, 256>>>(N);
    csr_count_kernel<<<512, 256>>>(dst, E);
    csr_scan_kernel<<<1, 1024>>>(N);
    csr_fill_kernel<<<512, 256>>>(src, dst, eattr, x, E);

    // Initial message aggregation (476-row table, cache-resident)
    gather_agg_kernel<<<2048, 256>>>(1, N);

    for (int p = 0; p < 4; p++) {
        update_mma_kernel<<<(N + 127) / 128, 512, SM_UPD>>>(x, bu2, N);
        gather_agg_kernel<<<2048, 256>>>(0, N);
    }

    zero_mol_kernel<<<64, 256>>>();
    mol_kernel<<<512, 256>>>(batch, N);
    readout_kernel<<<M, 256>>>(Wr1, br1, Wr2, br2, out);
}

// round 8
// speedup vs baseline: 2.0122x; 1.0386x over previous
#include <cuda_runtime.h>
#include <cuda_bf16.h>
#include <cstdint>

// ---------------------------------------------------------------------------
// BasicDMPNN on GB300 — round 8: 2-blocks/SM update kernel + fused mol pooling.
//   * update: 64 nodes/block, 256 threads, single 64KB weight buffer
//     (W1 -> GEMM1 -> overwrite with W2 -> 4x GEMM2), 96KB smem, occ 50%
//   * final gather reduces straight into g_mol (mol_kernel deleted)
//   * CSR gather-reduce + bf16x3 mma.sync (round-7 winners, unchanged math)
// ---------------------------------------------------------------------------

#define NMAX 50000
#define EMAX 800000
#define MMAX 2000
#define NTAB 476

__device__ __align__(16) float g_bias[NTAB * 128];     // ab@Wu1[:192]+bu1
__device__ __align__(16) float g_msgInit[NTAB * 128];  // relu(ab@Wi+bi)
__device__ __align__(16) float g_agg[NMAX * 128];
__device__ __align__(16) float g_msgTable[NMAX * 4 * 128];
__device__ __align__(16) float g_mol[MMAX * 128];
__device__ __align__(16) uint4 g_Wf1[4096];            // Wu1agg frag image (hi/lo)
__device__ __align__(16) uint4 g_Wf2[4096];            // Wu2 frag image (hi/lo)

// CSR scratch
__device__ int g_hist[NMAX];
__device__ int g_rowStart[NMAX + 1];
__device__ int g_cursor[NMAX];
__device__ int g_row0[EMAX];   // x[src]*4+attr  (init-message row ids)
__device__ int g_rowU[EMAX];   // src*4+attr     (update-message row ids)

// ---------------------------------------------------------------------------
__device__ __forceinline__ uint32_t pack_bf16x2(float e0, float e1) {
    __nv_bfloat162 p = __floats2bfloat162_rn(e0, e1);
    return *reinterpret_cast<uint32_t*>(&p);
}
__device__ __forceinline__ void split2(float e0, float e1,
                                       uint32_t& hi, uint32_t& lo) {
    float h0 = __bfloat162float(__float2bfloat16(e0));
    float h1 = __bfloat162float(__float2bfloat16(e1));
    hi = pack_bf16x2(h0, h1);
    lo = pack_bf16x2(e0 - h0, e1 - h1);
}
__device__ __forceinline__ void mma_bf16(float d[4], const uint32_t a[4],
                                         uint32_t b0, uint32_t b1) {
    asm volatile(
        "mma.sync.aligned.m16n8k16.row.col.f32.bf16.bf16.f32 "
        "{%0,%1,%2,%3}, {%4,%5,%6,%7}, {%8,%9}, {%0,%1,%2,%3};"
        : "+f"(d[0]), "+f"(d[1]), "+f"(d[2]), "+f"(d[3])
        : "r"(a[0]), "r"(a[1]), "r"(a[2]), "r"(a[3]), "r"(b0), "r"(b1));
}
__device__ __forceinline__ int aidx(int row, int kk) {
    return row * 64 + (kk ^ ((row & 7) << 2));
}

// ---------------------------------------------------------------------------
// CSR build
// ---------------------------------------------------------------------------
__global__ void csr_zero_kernel(int N) {
    for (int i = blockIdx.x * blockDim.x + threadIdx.x; i < N;
         i += gridDim.x * blockDim.x)
        g_hist[i] = 0;
}
__global__ void csr_count_kernel(const int* __restrict__ dst, int E) {
    for (int e = blockIdx.x * blockDim.x + threadIdx.x; e < E;
         e += gridDim.x * blockDim.x)
        atomicAdd(&g_hist[dst[e]], 1);
}
__global__ void __launch_bounds__(1024, 1) csr_scan_kernel(int N) {
    __shared__ int part[1024];
    int tid = threadIdx.x;
    int per = (N + 1023) / 1024;
    int start = tid * per;
    int sum = 0;
    for (int i = 0; i < per; i++) {
        int idx = start + i;
        if (idx < N) sum += g_hist[idx];
    }
    part[tid] = sum;
    __syncthreads();
    for (int off = 1; off < 1024; off <<= 1) {
        int v = (tid >= off) ? part[tid - off] : 0;
        __syncthreads();
        part[tid] += v;
        __syncthreads();
    }
    int run = tid ? part[tid - 1] : 0;
    for (int i = 0; i < per; i++) {
        int idx = start + i;
        if (idx < N) {
            g_rowStart[idx] = run;
            g_cursor[idx] = run;
            run += g_hist[idx];
        }
    }
    if (tid == 1023) g_rowStart[N] = part[1023];
}
__global__ void csr_fill_kernel(const int* __restrict__ src,
                                const int* __restrict__ dst,
                                const int* __restrict__ attr,
                                const int* __restrict__ x, int E) {
    for (int e = blockIdx.x * blockDim.x + threadIdx.x; e < E;
         e += gridDim.x * blockDim.x) {
        int d = dst[e];
        int s = src[e];
        int a = attr[e];
        int pos = atomicAdd(&g_cursor[d], 1);
        g_rowU[pos] = s * 4 + a;
        g_row0[pos] = x[s] * 4 + a;
    }
}

// ---------------------------------------------------------------------------
// Aggregation: warp per node, register reduce, no atomics on g_agg.
// mode 0: rows=g_row0,  table=g_msgInit,  out -> g_agg
// mode 1: rows=g_rowU,  table=g_msgTable, out -> g_agg
// mode 2: rows=g_rowU,  table=g_msgTable, out -> red.add g_mol[batch[n]]
__global__ void gather_agg_kernel(int mode, const int* __restrict__ batch, int N) {
    const int* __restrict__ rowids = (mode == 0) ? g_row0 : g_rowU;
    const float* __restrict__ table = (mode == 0) ? g_msgInit : g_msgTable;
    int lane = threadIdx.x & 31;
    int w = (blockIdx.x * blockDim.x + threadIdx.x) >> 5;
    int nw = (gridDim.x * blockDim.x) >> 5;
    for (int n = w; n < N; n += nw) {
        int s0 = g_rowStart[n];
        int s1 = g_rowStart[n + 1];
        float4 acc = make_float4(0.f, 0.f, 0.f, 0.f);
        int j = s0;
        for (; j + 2 <= s1; j += 2) {
            int r0 = __ldg(rowids + j);
            int r1 = __ldg(rowids + j + 1);
            float4 v0 = ((const float4*)(table + (size_t)r0 * 128))[lane];
            float4 v1 = ((const float4*)(table + (size_t)r1 * 128))[lane];
            acc.x += v0.x; acc.y += v0.y; acc.z += v0.z; acc.w += v0.w;
            acc.x += v1.x; acc.y += v1.y; acc.z += v1.z; acc.w += v1.w;
        }
        if (j < s1) {
            int r0 = __ldg(rowids + j);
            float4 v0 = ((const float4*)(table + (size_t)r0 * 128))[lane];
            acc.x += v0.x; acc.y += v0.y; acc.z += v0.z; acc.w += v0.w;
        }
        if (mode == 2) {
            float* outp = g_mol + (size_t)__ldg(batch + n) * 128 + lane * 4;
            asm volatile("red.global.add.v4.f32 [%0], {%1,%2,%3,%4};"
                         :: "l"(outp), "f"(acc.x), "f"(acc.y), "f"(acc.z), "f"(acc.w)
                         : "memory");
        } else {
            ((float4*)(g_agg + (size_t)n * 128))[lane] = acc;
        }
    }
}

// ---------------------------------------------------------------------------
// Build the two 476x128 tables (exact fp32).
__global__ void table_kernel(const float* __restrict__ atom_table,
                             const float* __restrict__ bond_table,
                             const float* __restrict__ Wi,
                             const float* __restrict__ bi,
                             const float* __restrict__ Wu1,
                             const float* __restrict__ bu1) {
    int t = blockIdx.x >> 2;
    int a = blockIdx.x & 3;
    int j = threadIdx.x;

    __shared__ float sAtom[128];
    __shared__ float sBond[64];
    sAtom[j] = atom_table[t * 128 + j];
    if (j < 64) sBond[j] = bond_table[a * 64 + j];
    __syncthreads();

    float accI = bi[j];
    float accB = bu1[j];
#pragma unroll 8
    for (int k = 0; k < 128; k++) {
        float av = sAtom[k];
        accI = fmaf(av, Wi[k * 128 + j], accI);
        accB = fmaf(av, Wu1[k * 128 + j], accB);
    }
#pragma unroll 8
    for (int k = 0; k < 64; k++) {
        float bv = sBond[k];
        accI = fmaf(bv, Wi[(128 + k) * 128 + j], accI);
        accB = fmaf(bv, Wu1[(128 + k) * 128 + j], accB);
    }
    g_msgInit[blockIdx.x * 128 + j] = fmaxf(accI, 0.f);
    g_bias[blockIdx.x * 128 + j] = accB;
}

// ---------------------------------------------------------------------------
// Pack W (k-major [128,128]) into fragment-ordered bf16 hi/lo images.
__global__ void prep_wfrag_kernel(const float* __restrict__ W1,
                                  const float* __restrict__ W2) {
    int i = blockIdx.x * blockDim.x + threadIdx.x;
    if (i >= 4096) return;
    int lane = i & 31;
    int ntile = (i >> 5) & 15;
    int ks = i >> 9;
    int k0 = ks * 16 + (lane & 3) * 2;
    int n = ntile * 8 + (lane >> 2);

    const float* Ws[2] = {W1, W2};
    uint4* imgs[2] = {g_Wf1, g_Wf2};
#pragma unroll
    for (int m = 0; m < 2; m++) {
        const float* W = Ws[m];
        uint4 v;
        split2(W[k0 * 128 + n], W[(k0 + 1) * 128 + n], v.x, v.z);
        split2(W[(k0 + 8) * 128 + n], W[(k0 + 9) * 128 + n], v.y, v.w);
        imgs[m][i] = v;
    }
}

// ---------------------------------------------------------------------------
// 64x128 @ 128x128 bf16x3 GEMM. Warp (wm 0..1, wn 0..3): 32 rows x 32 cols.
__device__ __forceinline__ void gemm_bf16x3(const uint32_t* __restrict__ sAhi,
                                            const uint32_t* __restrict__ sAlo,
                                            const uint4* __restrict__ sW,
                                            int wm, int wn, int lane,
                                            float D[2][4][4]) {
#pragma unroll
    for (int mt = 0; mt < 2; mt++)
#pragma unroll
        for (int nt = 0; nt < 4; nt++)
#pragma unroll
            for (int q = 0; q < 4; q++) D[mt][nt][q] = 0.f;

#pragma unroll
    for (int ks = 0; ks < 8; ks++) {
        uint32_t Ahi[2][4], Alo[2][4];
#pragma unroll
        for (int mt = 0; mt < 2; mt++) {
            int r = wm * 32 + mt * 16 + (lane >> 2);
            int kk = ks * 8 + (lane & 3);
            Ahi[mt][0] = sAhi[aidx(r, kk)];
            Ahi[mt][1] = sAhi[aidx(r + 8, kk)];
            Ahi[mt][2] = sAhi[aidx(r, kk + 4)];
            Ahi[mt][3] = sAhi[aidx(r + 8, kk + 4)];
            Alo[mt][0] = sAlo[aidx(r, kk)];
            Alo[mt][1] = sAlo[aidx(r + 8, kk)];
            Alo[mt][2] = sAlo[aidx(r, kk + 4)];
            Alo[mt][3] = sAlo[aidx(r + 8, kk + 4)];
        }
#pragma unroll
        for (int nt = 0; nt < 4; nt++) {
            uint4 B = sW[(ks * 16 + wn * 4 + nt) * 32 + lane];
            mma_bf16(D[0][nt], Ahi[0], B.x, B.y);   // hi*hi
            mma_bf16(D[1][nt], Ahi[1], B.x, B.y);
            mma_bf16(D[0][nt], Ahi[0], B.z, B.w);   // hi*lo
            mma_bf16(D[1][nt], Ahi[1], B.z, B.w);
            mma_bf16(D[0][nt], Alo[0], B.x, B.y);   // lo*hi
            mma_bf16(D[1][nt], Alo[1], B.x, B.y);
        }
    }
}

// ---------------------------------------------------------------------------
// Update pass: 64 nodes/block, 256 threads, 2 blocks/SM.
// smem: sAhi 16KB + sAlo 16KB + sW 64KB (W1 then W2) = 96KB.
#define SM_UPD (16384 + 16384 + 65536)

__global__ void __launch_bounds__(256, 2)
update_mma_kernel(const int* __restrict__ x, const float* __restrict__ bu2, int N) {
    extern __shared__ uint32_t smem[];
    uint32_t* sAhi = smem;                 // 4096 words
    uint32_t* sAlo = smem + 4096;          // 4096 words
    uint4* sW = (uint4*)(smem + 8192);     // 4096 uint4 (64KB)
    __shared__ int sX[64];

    int tid = threadIdx.x;
    int lane = tid & 31;
    int wid = tid >> 5;
    int wm = wid >> 2;     // 0..1
    int wn = wid & 3;      // 0..3
    int nb = blockIdx.x * 64;

    // W1 + activations
#pragma unroll
    for (int i = tid; i < 4096; i += 256) sW[i] = g_Wf1[i];
    {
        const float4* agg4 = (const float4*)g_agg;
#pragma unroll
        for (int i = tid; i < 2048; i += 256) {
            int row = i >> 5;
            int q = i & 31;
            float4 v = (nb + row < N) ? agg4[(size_t)(nb + row) * 32 + q]
                                      : make_float4(0.f, 0.f, 0.f, 0.f);
            uint32_t h0, l0, h1, l1;
            split2(v.x, v.y, h0, l0);
            split2(v.z, v.w, h1, l1);
            int p = aidx(row, 2 * q);
            sAhi[p] = h0; sAhi[p + 1] = h1;
            sAlo[p] = l0; sAlo[p + 1] = l1;
        }
        if (tid < 64) sX[tid] = (nb + tid < N) ? x[nb + tid] * 4 : 0;
    }
    __syncthreads();

    // GEMM1: D1 = agg @ Wu1agg (registers)
    float D1[2][4][4];
    gemm_bf16x3(sAhi, sAlo, sW, wm, wn, lane, D1);
    __syncthreads();   // all warps done with sW (W1) and sA reads

    float2 b2v[4];
#pragma unroll
    for (int nt = 0; nt < 4; nt++)
        b2v[nt] = *(const float2*)(bu2 + (wn * 4 + nt) * 8 + (lane & 3) * 2);

    int r0 = wm * 32 + (lane >> 2);
    int c0 = (lane & 3) * 2;

    for (int a = 0; a < 4; a++) {
        if (a == 0) {   // overwrite weight buffer with W2 (serves all 4 attrs)
#pragma unroll
            for (int i = tid; i < 4096; i += 256) sW[i] = g_Wf2[i];
        }
        // h = relu(D1 + bias[x*4+a]) -> split -> sA
#pragma unroll
        for (int mt = 0; mt < 2; mt++) {
#pragma unroll
            for (int hh = 0; hh < 2; hh++) {
                int r = r0 + mt * 16 + hh * 8;
                const float* bp = g_bias + (size_t)(sX[r] + a) * 128;
#pragma unroll
                for (int nt = 0; nt < 4; nt++) {
                    int col = (wn * 4 + nt) * 8 + c0;
                    float2 b = *(const float2*)(bp + col);
                    float h0 = fmaxf(D1[mt][nt][hh * 2] + b.x, 0.f);
                    float h1 = fmaxf(D1[mt][nt][hh * 2 + 1] + b.y, 0.f);
                    uint32_t ph, pl;
                    split2(h0, h1, ph, pl);
                    int p = aidx(r, col >> 1);
                    sAhi[p] = ph;
                    sAlo[p] = pl;
                }
            }
        }
        __syncthreads();

        // GEMM2: D2 = h @ Wu2
        float D2[2][4][4];
        gemm_bf16x3(sAhi, sAlo, sW, wm, wn, lane, D2);

        // msg = relu(D2 + bu2) -> g_msgTable
#pragma unroll
        for (int mt = 0; mt < 2; mt++) {
#pragma unroll
            for (int hh = 0; hh < 2; hh++) {
                int r = r0 + mt * 16 + hh * 8;
                int n = nb + r;
                if (n < N) {
                    float* mp = g_msgTable + ((size_t)n * 4 + a) * 128;
#pragma unroll
                    for (int nt = 0; nt < 4; nt++) {
                        int col = (wn * 4 + nt) * 8 + c0;
                        float2 o;
                        o.x = fmaxf(D2[mt][nt][hh * 2] + b2v[nt].x, 0.f);
                        o.y = fmaxf(D2[mt][nt][hh * 2 + 1] + b2v[nt].y, 0.f);
                        *(float2*)(mp + col) = o;
                    }
                }
            }
        }
        __syncthreads();   // gemm2 reads done before next h write
    }
}

// ---------------------------------------------------------------------------
__global__ void zero_mol_kernel() {
    float4 z = make_float4(0.f, 0.f, 0.f, 0.f);
    float4* p = (float4*)g_mol;
    int n4 = MMAX * 32;
    for (int i = blockIdx.x * blockDim.x + threadIdx.x; i < n4;
         i += gridDim.x * blockDim.x)
        p[i] = z;
}

// ---------------------------------------------------------------------------
__global__ void readout_kernel(const float* __restrict__ Wr1,
                               const float* __restrict__ br1,
                               const float* __restrict__ Wr2,
                               const float* __restrict__ br2,
                               float* __restrict__ out) {
    int m = blockIdx.x;
    int tid = threadIdx.x;  // 256
    __shared__ float sMol[128];
    __shared__ float sRed[8];
    if (tid < 128) sMol[tid] = g_mol[m * 128 + tid];
    __syncthreads();

    float part = 0.f;
#pragma unroll
    for (int jj = 0; jj < 2; jj++) {
        int j = tid + jj * 256;
        float h = br1[j];
#pragma unroll 8
        for (int k = 0; k < 128; k++)
            h = fmaf(sMol[k], Wr1[k * 512 + j], h);
        h = fmaxf(h, 0.f);
        part = fmaf(h, Wr2[j], part);
    }
#pragma unroll
    for (int off = 16; off; off >>= 1)
        part += __shfl_down_sync(0xffffffffu, part, off);
    if ((tid & 31) == 0) sRed[tid >> 5] = part;
    __syncthreads();
    if (tid == 0) {
        float s = br2[0];
#pragma unroll
        for (int i = 0; i < 8; i++) s += sRed[i];
        out[m] = s;
    }
}

// ---------------------------------------------------------------------------
extern "C" void kernel_launch(void* const* d_in, const int* in_sizes, int n_in,
                              void* d_out, int out_size) {
    const int*   x          = (const int*)d_in[0];
    const int*   eattr      = (const int*)d_in[1];
    const int*   eidx       = (const int*)d_in[2];
    const int*   batch      = (const int*)d_in[3];
    const float* atom_table = (const float*)d_in[4];
    const float* bond_table = (const float*)d_in[5];
    const float* Wi         = (const float*)d_in[6];
    const float* bi         = (const float*)d_in[7];
    const float* Wu1        = (const float*)d_in[8];
    const float* bu1        = (const float*)d_in[9];
    const float* Wu2        = (const float*)d_in[10];
    const float* bu2        = (const float*)d_in[11];
    const float* Wr1        = (const float*)d_in[12];
    const float* br1        = (const float*)d_in[13];
    const float* Wr2        = (const float*)d_in[14];
    const float* br2        = (const float*)d_in[15];
    float* out = (float*)d_out;

    int N = in_sizes[0];
    int E = in_sizes[1];
    int M = out_size;
    const int* src = eidx;
    const int* dst = eidx + E;

    cudaFuncSetAttribute(update_mma_kernel,
                         cudaFuncAttributeMaxDynamicSharedMemorySize, SM_UPD);

    // Tables + weight frag images + CSR build
    table_kernel<<<NTAB, 128>>>(atom_table, bond_table, Wi, bi, Wu1, bu1);
    prep_wfrag_kernel<<<16, 256>>>(Wu1 + 192 * 128, Wu2);
    csr_zero_kernel<<<128, 256>>>(N);
    csr_count_kernel<<<512, 256>>>(dst, E);
    csr_scan_kernel<<<1, 1024>>>(N);
    csr_fill_kernel<<<512, 256>>>(src, dst, eattr, x, E);
    zero_mol_kernel<<<64, 256>>>();

    // Initial message aggregation (476-row table, cache-resident)
    gather_agg_kernel<<<2048, 256>>>(0, batch, N);

    for (int p = 0; p < 4; p++) {
        update_mma_kernel<<<(N + 63) / 64, 256, SM_UPD>>>(x, bu2, N);
        gather_agg_kernel<<<2048, 256>>>((p < 3) ? 1 : 2, batch, N);
    }

    readout_kernel<<<M, 256>>>(Wr1, br1, Wr2, br2, out);
}